// round 16
// baseline (speedup 1.0000x reference)
#include <cuda_runtime.h>
#include <cuda_bf16.h>
#include <cstdint>

// EfficientReynoldsFeatureOperator:
//   x:  (B=8, N=8192, D=512) fp32
//   W:  (512, 128) fp32, pw: (128) fp32
//   out:(B, N, R) fp32,  out[b,n,r] = (mean_n(x[b]) @ W)[r] * pw[r]
// Using mean_n(x @ W) == (mean_n x) @ W.
//
// Round-15 PDL chain (36.86us) with triggers moved to kernel START:
// successors launch while predecessors run, park at
// cudaGridDependencySynchronize() (which still guarantees completion +
// memory visibility), so every launch ramp is fully hidden.

#define B_DIM 8
#define N_DIM 8192
#define D_DIM 512
#define R_DIM 128
#define CHUNKS 256
#define ROWS_PER_CHUNK (N_DIM / CHUNKS)     // 32
#define G2 32                                // k2a blocks per batch
#define CHUNKS_PER_G2 (CHUNKS / G2)          // 8

__device__ float g_partial[B_DIM * CHUNKS * D_DIM];   // 4 MB scratch (L2-hot)
__device__ float g_p2[B_DIM * G2 * D_DIM];            // 512 KB
__device__ float g_y[B_DIM * R_DIM];                  // 4 KB

// ---------------------------------------------------------------------------
// K1: partial column sums of x over n. (proven 5.8 TB/s body)
// grid = (CHUNKS, B) = 2048 blocks, 128 threads.
// ---------------------------------------------------------------------------
__global__ __launch_bounds__(128, 8) void k1_colsum_partial(const float* __restrict__ x) {
    cudaTriggerProgrammaticLaunchCompletion();   // let k2a prelaunch now

    const int chunk = blockIdx.x;
    const int b     = blockIdx.y;
    const int t     = threadIdx.x;            // 0..127

    const float4* xrow = reinterpret_cast<const float4*>(
        x + ((size_t)b * N_DIM + (size_t)chunk * ROWS_PER_CHUNK) * D_DIM);

    float4 a0 = make_float4(0.f, 0.f, 0.f, 0.f);
    float4 a1 = make_float4(0.f, 0.f, 0.f, 0.f);

#pragma unroll
    for (int i = 0; i < ROWS_PER_CHUNK; i += 8) {
        float4 v0 = __ldcs(&xrow[(size_t)(i + 0) * 128 + t]);
        float4 v1 = __ldcs(&xrow[(size_t)(i + 1) * 128 + t]);
        float4 v2 = __ldcs(&xrow[(size_t)(i + 2) * 128 + t]);
        float4 v3 = __ldcs(&xrow[(size_t)(i + 3) * 128 + t]);
        float4 v4 = __ldcs(&xrow[(size_t)(i + 4) * 128 + t]);
        float4 v5 = __ldcs(&xrow[(size_t)(i + 5) * 128 + t]);
        float4 v6 = __ldcs(&xrow[(size_t)(i + 6) * 128 + t]);
        float4 v7 = __ldcs(&xrow[(size_t)(i + 7) * 128 + t]);
        a0.x += v0.x; a0.y += v0.y; a0.z += v0.z; a0.w += v0.w;
        a1.x += v1.x; a1.y += v1.y; a1.z += v1.z; a1.w += v1.w;
        a0.x += v2.x; a0.y += v2.y; a0.z += v2.z; a0.w += v2.w;
        a1.x += v3.x; a1.y += v3.y; a1.z += v3.z; a1.w += v3.w;
        a0.x += v4.x; a0.y += v4.y; a0.z += v4.z; a0.w += v4.w;
        a1.x += v5.x; a1.y += v5.y; a1.z += v5.z; a1.w += v5.w;
        a0.x += v6.x; a0.y += v6.y; a0.z += v6.z; a0.w += v6.w;
        a1.x += v7.x; a1.y += v7.y; a1.z += v7.z; a1.w += v7.w;
    }
    a0.x += a1.x; a0.y += a1.y; a0.z += a1.z; a0.w += a1.w;

    float4* p = reinterpret_cast<float4*>(
        g_partial + ((size_t)b * CHUNKS + chunk) * D_DIM);
    p[t] = a0;
}

// ---------------------------------------------------------------------------
// K2a: first-level partial reduction, 256 blocks. (round-5 body + PDL)
// ---------------------------------------------------------------------------
__global__ __launch_bounds__(128) void k2a_reduce(void) {
    cudaTriggerProgrammaticLaunchCompletion();   // let k2b prelaunch now

    const int j  = blockIdx.x;
    const int b  = blockIdx.y;
    const int d4 = threadIdx.x;

    const float4* base = reinterpret_cast<const float4*>(
        g_partial + ((size_t)b * CHUNKS + (size_t)j * CHUNKS_PER_G2) * D_DIM);

    cudaGridDependencySynchronize();            // wait for k1's stores

    float4 acc = make_float4(0.f, 0.f, 0.f, 0.f);
#pragma unroll
    for (int c = 0; c < CHUNKS_PER_G2; ++c) {
        float4 v = base[(size_t)c * 128 + d4];
        acc.x += v.x; acc.y += v.y; acc.z += v.z; acc.w += v.w;
    }
    float4* p = reinterpret_cast<float4*>(
        g_p2 + ((size_t)b * G2 + j) * D_DIM);
    p[d4] = acc;
}

// ---------------------------------------------------------------------------
// K2b: per batch finish + projection. grid = B, 512 thr. (round-5 body + PDL)
// ---------------------------------------------------------------------------
__global__ __launch_bounds__(512) void k2b_finish_and_project(
    const float* __restrict__ W, const float* __restrict__ pw) {
    cudaTriggerProgrammaticLaunchCompletion();   // let k3 prelaunch now

    __shared__ float s_part[4][D_DIM];
    __shared__ float s_mean[D_DIM];
    __shared__ float s_red[16][R_DIM];
    const int b = blockIdx.x;
    const int t = threadIdx.x;
    const int g  = t >> 7;        // 0..3
    const int d4 = t & 127;       // 0..127

    const float4* pbase = reinterpret_cast<const float4*>(
        g_p2 + (size_t)b * G2 * D_DIM);

    cudaGridDependencySynchronize();            // wait for k2a's stores

    float4 acc = make_float4(0.f, 0.f, 0.f, 0.f);
#pragma unroll
    for (int c = g; c < G2; c += 4) {
        float4 v = pbase[(size_t)c * 128 + d4];
        acc.x += v.x; acc.y += v.y; acc.z += v.z; acc.w += v.w;
    }
    s_part[g][4 * d4 + 0] = acc.x;
    s_part[g][4 * d4 + 1] = acc.y;
    s_part[g][4 * d4 + 2] = acc.z;
    s_part[g][4 * d4 + 3] = acc.w;
    __syncthreads();

    s_mean[t] = (s_part[0][t] + s_part[1][t] + s_part[2][t] + s_part[3][t])
                * (1.0f / (float)N_DIM);
    __syncthreads();

    const int w    = t >> 5;
    const int lane = t & 31;
    float p0 = 0.f, p1 = 0.f, p2 = 0.f, p3 = 0.f;
#pragma unroll
    for (int i = 0; i < 32; ++i) {
        const int d = w * 32 + i;
        const float m = s_mean[d];
        const float* Wr = W + (size_t)d * R_DIM;
        p0 = fmaf(m, __ldg(&Wr[lane]),      p0);
        p1 = fmaf(m, __ldg(&Wr[32 + lane]), p1);
        p2 = fmaf(m, __ldg(&Wr[64 + lane]), p2);
        p3 = fmaf(m, __ldg(&Wr[96 + lane]), p3);
    }
    s_red[w][lane]      = p0;
    s_red[w][32 + lane] = p1;
    s_red[w][64 + lane] = p2;
    s_red[w][96 + lane] = p3;
    __syncthreads();

    if (t < R_DIM) {
        float y = 0.f;
#pragma unroll
        for (int k = 0; k < 16; ++k)
            y += s_red[k][t];
        g_y[b * R_DIM + t] = y * pw[t];
    }
}

// ---------------------------------------------------------------------------
// K3: broadcast y. (round-5 proven 8-ILP body + PDL)
// ---------------------------------------------------------------------------
__global__ __launch_bounds__(256) void k3_broadcast(float4* __restrict__ out) {
    const int tid = blockIdx.x * blockDim.x + threadIdx.x;  // 0..262143
    const int r4  = tid & (R_DIM / 4 - 1);

    cudaGridDependencySynchronize();            // wait for k2b's g_y stores

    const float4* y4 = reinterpret_cast<const float4*>(g_y);
#pragma unroll
    for (int b = 0; b < B_DIM; ++b) {
        float4 v = __ldg(&y4[b * (R_DIM / 4) + r4]);
        out[(size_t)b * (N_DIM * R_DIM / 4) + tid] = v;
    }
}

// ---------------------------------------------------------------------------
extern "C" void kernel_launch(void* const* d_in, const int* in_sizes, int n_in,
                              void* d_out, int out_size) {
    const float* x  = (const float*)d_in[0];
    const float* W  = (const float*)d_in[1];
    const float* pw = (const float*)d_in[2];
    float4* out4    = (float4*)d_out;

    (void)in_sizes; (void)n_in; (void)out_size;

    cudaLaunchAttribute pdl_attr[1];
    pdl_attr[0].id = cudaLaunchAttributeProgrammaticStreamSerialization;
    pdl_attr[0].val.programmaticStreamSerializationAllowed = 1;

    // k1: plain launch (head of chain)
    k1_colsum_partial<<<dim3(CHUNKS, B_DIM), 128>>>(x);

    // k2a: PDL on k1
    {
        cudaLaunchConfig_t cfg = {};
        cfg.gridDim  = dim3(G2, B_DIM);
        cfg.blockDim = dim3(128);
        cfg.stream   = (cudaStream_t)0;
        cfg.attrs    = pdl_attr;
        cfg.numAttrs = 1;
        cudaLaunchKernelEx(&cfg, k2a_reduce);
    }
    // k2b: PDL on k2a
    {
        cudaLaunchConfig_t cfg = {};
        cfg.gridDim  = dim3(B_DIM);
        cfg.blockDim = dim3(512);
        cfg.stream   = (cudaStream_t)0;
        cfg.attrs    = pdl_attr;
        cfg.numAttrs = 1;
        cudaLaunchKernelEx(&cfg, k2b_finish_and_project, W, pw);
    }
    // k3: PDL on k2b
    {
        cudaLaunchConfig_t cfg = {};
        cfg.gridDim  = dim3((N_DIM * R_DIM / 4) / 256);   // 1024 blocks
        cfg.blockDim = dim3(256);
        cfg.stream   = (cudaStream_t)0;
        cfg.attrs    = pdl_attr;
        cfg.numAttrs = 1;
        cudaLaunchKernelEx(&cfg, k3_broadcast, out4);
    }
}

// round 17
// speedup vs baseline: 1.1181x; 1.1181x over previous
#include <cuda_runtime.h>
#include <cuda_bf16.h>
#include <cstdint>

// EfficientReynoldsFeatureOperator:
//   x:  (B=8, N=8192, D=512) fp32
//   W:  (512, 128) fp32, pw: (128) fp32
//   out:(B, N, R) fp32,  out[b,n,r] = (mean_n(x[b]) @ W)[r] * pw[r]
// Using mean_n(x @ W) == (mean_n x) @ W.
//
// Round-15 winning PDL chain (36.86us). Triggers at kernel END (round-16's
// trigger-at-top let successor grids prelaunch and steal residency from k1's
// second wave: -4.3us). Successors' grid-dep-sync sits after their preamble
// so address math overlaps the predecessor's tail at zero risk.

#define B_DIM 8
#define N_DIM 8192
#define D_DIM 512
#define R_DIM 128
#define CHUNKS 256
#define ROWS_PER_CHUNK (N_DIM / CHUNKS)     // 32
#define G2 32                                // k2a blocks per batch
#define CHUNKS_PER_G2 (CHUNKS / G2)          // 8

__device__ float g_partial[B_DIM * CHUNKS * D_DIM];   // 4 MB scratch (L2-hot)
__device__ float g_p2[B_DIM * G2 * D_DIM];            // 512 KB
__device__ float g_y[B_DIM * R_DIM];                  // 4 KB

// ---------------------------------------------------------------------------
// K1: partial column sums of x over n. (proven 5.8 TB/s body)
// grid = (CHUNKS, B) = 2048 blocks, 128 threads.
// ---------------------------------------------------------------------------
__global__ __launch_bounds__(128, 8) void k1_colsum_partial(const float* __restrict__ x) {
    const int chunk = blockIdx.x;
    const int b     = blockIdx.y;
    const int t     = threadIdx.x;            // 0..127

    const float4* xrow = reinterpret_cast<const float4*>(
        x + ((size_t)b * N_DIM + (size_t)chunk * ROWS_PER_CHUNK) * D_DIM);

    float4 a0 = make_float4(0.f, 0.f, 0.f, 0.f);
    float4 a1 = make_float4(0.f, 0.f, 0.f, 0.f);

#pragma unroll
    for (int i = 0; i < ROWS_PER_CHUNK; i += 8) {
        float4 v0 = __ldcs(&xrow[(size_t)(i + 0) * 128 + t]);
        float4 v1 = __ldcs(&xrow[(size_t)(i + 1) * 128 + t]);
        float4 v2 = __ldcs(&xrow[(size_t)(i + 2) * 128 + t]);
        float4 v3 = __ldcs(&xrow[(size_t)(i + 3) * 128 + t]);
        float4 v4 = __ldcs(&xrow[(size_t)(i + 4) * 128 + t]);
        float4 v5 = __ldcs(&xrow[(size_t)(i + 5) * 128 + t]);
        float4 v6 = __ldcs(&xrow[(size_t)(i + 6) * 128 + t]);
        float4 v7 = __ldcs(&xrow[(size_t)(i + 7) * 128 + t]);
        a0.x += v0.x; a0.y += v0.y; a0.z += v0.z; a0.w += v0.w;
        a1.x += v1.x; a1.y += v1.y; a1.z += v1.z; a1.w += v1.w;
        a0.x += v2.x; a0.y += v2.y; a0.z += v2.z; a0.w += v2.w;
        a1.x += v3.x; a1.y += v3.y; a1.z += v3.z; a1.w += v3.w;
        a0.x += v4.x; a0.y += v4.y; a0.z += v4.z; a0.w += v4.w;
        a1.x += v5.x; a1.y += v5.y; a1.z += v5.z; a1.w += v5.w;
        a0.x += v6.x; a0.y += v6.y; a0.z += v6.z; a0.w += v6.w;
        a1.x += v7.x; a1.y += v7.y; a1.z += v7.z; a1.w += v7.w;
    }
    a0.x += a1.x; a0.y += a1.y; a0.z += a1.z; a0.w += a1.w;

    float4* p = reinterpret_cast<float4*>(
        g_partial + ((size_t)b * CHUNKS + chunk) * D_DIM);
    p[t] = a0;

    cudaTriggerProgrammaticLaunchCompletion();
}

// ---------------------------------------------------------------------------
// K2a: first-level partial reduction, 256 blocks.
// ---------------------------------------------------------------------------
__global__ __launch_bounds__(128) void k2a_reduce(void) {
    const int j  = blockIdx.x;
    const int b  = blockIdx.y;
    const int d4 = threadIdx.x;

    const float4* base = reinterpret_cast<const float4*>(
        g_partial + ((size_t)b * CHUNKS + (size_t)j * CHUNKS_PER_G2) * D_DIM);

    cudaGridDependencySynchronize();            // wait for k1's stores

    float4 acc = make_float4(0.f, 0.f, 0.f, 0.f);
#pragma unroll
    for (int c = 0; c < CHUNKS_PER_G2; ++c) {
        float4 v = base[(size_t)c * 128 + d4];
        acc.x += v.x; acc.y += v.y; acc.z += v.z; acc.w += v.w;
    }
    float4* p = reinterpret_cast<float4*>(
        g_p2 + ((size_t)b * G2 + j) * D_DIM);
    p[d4] = acc;

    cudaTriggerProgrammaticLaunchCompletion();
}

// ---------------------------------------------------------------------------
// K2b: per batch finish + projection. grid = B, 512 thr.
// ---------------------------------------------------------------------------
__global__ __launch_bounds__(512) void k2b_finish_and_project(
    const float* __restrict__ W, const float* __restrict__ pw) {
    __shared__ float s_part[4][D_DIM];
    __shared__ float s_mean[D_DIM];
    __shared__ float s_red[16][R_DIM];
    const int b = blockIdx.x;
    const int t = threadIdx.x;
    const int g  = t >> 7;        // 0..3
    const int d4 = t & 127;       // 0..127

    const float4* pbase = reinterpret_cast<const float4*>(
        g_p2 + (size_t)b * G2 * D_DIM);

    cudaGridDependencySynchronize();            // wait for k2a's stores

    float4 acc = make_float4(0.f, 0.f, 0.f, 0.f);
#pragma unroll
    for (int c = g; c < G2; c += 4) {
        float4 v = pbase[(size_t)c * 128 + d4];
        acc.x += v.x; acc.y += v.y; acc.z += v.z; acc.w += v.w;
    }
    s_part[g][4 * d4 + 0] = acc.x;
    s_part[g][4 * d4 + 1] = acc.y;
    s_part[g][4 * d4 + 2] = acc.z;
    s_part[g][4 * d4 + 3] = acc.w;
    __syncthreads();

    s_mean[t] = (s_part[0][t] + s_part[1][t] + s_part[2][t] + s_part[3][t])
                * (1.0f / (float)N_DIM);
    __syncthreads();

    const int w    = t >> 5;
    const int lane = t & 31;
    float p0 = 0.f, p1 = 0.f, p2 = 0.f, p3 = 0.f;
#pragma unroll
    for (int i = 0; i < 32; ++i) {
        const int d = w * 32 + i;
        const float m = s_mean[d];
        const float* Wr = W + (size_t)d * R_DIM;
        p0 = fmaf(m, __ldg(&Wr[lane]),      p0);
        p1 = fmaf(m, __ldg(&Wr[32 + lane]), p1);
        p2 = fmaf(m, __ldg(&Wr[64 + lane]), p2);
        p3 = fmaf(m, __ldg(&Wr[96 + lane]), p3);
    }
    s_red[w][lane]      = p0;
    s_red[w][32 + lane] = p1;
    s_red[w][64 + lane] = p2;
    s_red[w][96 + lane] = p3;
    __syncthreads();

    if (t < R_DIM) {
        float y = 0.f;
#pragma unroll
        for (int k = 0; k < 16; ++k)
            y += s_red[k][t];
        g_y[b * R_DIM + t] = y * pw[t];
    }

    cudaTriggerProgrammaticLaunchCompletion();
}

// ---------------------------------------------------------------------------
// K3: broadcast y. (round-5 proven 8-ILP body)
// ---------------------------------------------------------------------------
__global__ __launch_bounds__(256) void k3_broadcast(float4* __restrict__ out) {
    const int tid = blockIdx.x * blockDim.x + threadIdx.x;  // 0..262143
    const int r4  = tid & (R_DIM / 4 - 1);

    cudaGridDependencySynchronize();            // wait for k2b's g_y stores

    const float4* y4 = reinterpret_cast<const float4*>(g_y);
#pragma unroll
    for (int b = 0; b < B_DIM; ++b) {
        float4 v = __ldg(&y4[b * (R_DIM / 4) + r4]);
        out[(size_t)b * (N_DIM * R_DIM / 4) + tid] = v;
    }
}

// ---------------------------------------------------------------------------
extern "C" void kernel_launch(void* const* d_in, const int* in_sizes, int n_in,
                              void* d_out, int out_size) {
    const float* x  = (const float*)d_in[0];
    const float* W  = (const float*)d_in[1];
    const float* pw = (const float*)d_in[2];
    float4* out4    = (float4*)d_out;

    (void)in_sizes; (void)n_in; (void)out_size;

    cudaLaunchAttribute pdl_attr[1];
    pdl_attr[0].id = cudaLaunchAttributeProgrammaticStreamSerialization;
    pdl_attr[0].val.programmaticStreamSerializationAllowed = 1;

    // k1: plain launch (head of chain)
    k1_colsum_partial<<<dim3(CHUNKS, B_DIM), 128>>>(x);

    // k2a: PDL on k1
    {
        cudaLaunchConfig_t cfg = {};
        cfg.gridDim  = dim3(G2, B_DIM);
        cfg.blockDim = dim3(128);
        cfg.stream   = (cudaStream_t)0;
        cfg.attrs    = pdl_attr;
        cfg.numAttrs = 1;
        cudaLaunchKernelEx(&cfg, k2a_reduce);
    }
    // k2b: PDL on k2a
    {
        cudaLaunchConfig_t cfg = {};
        cfg.gridDim  = dim3(B_DIM);
        cfg.blockDim = dim3(512);
        cfg.stream   = (cudaStream_t)0;
        cfg.attrs    = pdl_attr;
        cfg.numAttrs = 1;
        cudaLaunchKernelEx(&cfg, k2b_finish_and_project, W, pw);
    }
    // k3: PDL on k2b
    {
        cudaLaunchConfig_t cfg = {};
        cfg.gridDim  = dim3((N_DIM * R_DIM / 4) / 256);   // 1024 blocks
        cfg.blockDim = dim3(256);
        cfg.stream   = (cudaStream_t)0;
        cfg.attrs    = pdl_attr;
        cfg.numAttrs = 1;
        cudaLaunchKernelEx(&cfg, k3_broadcast, out4);
    }
}